// round 14
// baseline (speedup 1.0000x reference)
#include <cuda_runtime.h>
#include <cuda_fp16.h>
#include <cstdint>

// ---------------------------------------------------------------------------
// SimpleGCN R13:
//  (a) GEMM register tile 4x8 (1.5 B smem per FMA, was 2.0) — R12 ncu showed
//      L1 cost follows data volume, not LDS instruction count.
//  (b) h1/h2 stored as fp16 mirrors ONLY; agg gathers read fp16, accumulate
//      fp32 (halves the LTS-bound gather traffic; output abs err ~1e-4 vs
//      log-softmax magnitude ~4 -> rel err ~3e-5, 30x under budget).
// ---------------------------------------------------------------------------

#define NMAX 100000
#define EMAX 1600000
#define F_IN 128
#define F_MID 128
#define F_OUT 64

#define SCAN_CHUNK 1024
#define NBLK_SCAN ((NMAX + SCAN_CHUNK - 1) / SCAN_CHUNK)

#define KCH 32     // GEMM k-chunk
#define PA 36      // A-tile pitch (32 + 4)
#define PW 68      // W-tile pitch (64 + 4)

__device__ __align__(16) int    g_src[EMAX];
__device__ __align__(16) int    g_dst[EMAX];
__device__ __align__(16) int    g_csrc[EMAX];
__device__ __align__(16) int    g_deg[NMAX];
__device__ __align__(16) int    g_rowptr[NMAX + 1];
__device__ __align__(16) int    g_cursor[NMAX];
__device__ __align__(16) int    g_bsum[NBLK_SCAN];
__device__ __align__(16) int    g_boff[NBLK_SCAN];
__device__ __align__(16) float  g_dinv[NMAX];
__device__ __align__(16) __half g_h1h[(size_t)NMAX * F_MID];  // x@W1, fp16
__device__ __align__(16) float  g_a1[(size_t)NMAX * F_MID];   // relu(agg+b1)
__device__ __align__(16) __half g_h2h[(size_t)NMAX * F_OUT];  // a1@W2, fp16
__device__ int g_is64;

// ---------------------------------------------------------------------------
__global__ void detect_kernel(const int* __restrict__ ei32) {
    if (threadIdx.x == 0 && blockIdx.x == 0) {
        int allzero = 1;
        for (int i = 0; i < 64; i++)
            if (ei32[2 * i + 1] != 0) { allzero = 0; break; }
        g_is64 = allzero;
    }
}

__global__ void zero_deg_kernel(int N) {
    int i = blockIdx.x * blockDim.x + threadIdx.x;
    if (i < N) g_deg[i] = 0;
}

__global__ void edge_prep_kernel(const void* __restrict__ ei_raw, int E, int N) {
    const int is64 = g_is64;
    const int stride = gridDim.x * blockDim.x;
    const int* __restrict__ p32 = (const int*)ei_raw;
    const long long* __restrict__ p64 = (const long long*)ei_raw;
    for (int e = blockIdx.x * blockDim.x + threadIdx.x; e < E; e += stride) {
        int s, d;
        if (is64) {
            s = (int)p64[e];
            d = (int)p64[(size_t)E + e];
        } else {
            s = p32[e];
            d = p32[(size_t)E + e];
        }
        s = min(max(s, 0), N - 1);
        d = min(max(d, 0), N - 1);
        g_src[e] = s;
        g_dst[e] = d;
        atomicAdd(&g_deg[d], 1);
    }
}

// ---------------------------------------------------------------------------
// GEMM1: h1h = fp16(x @ W1). Block tile 128x64, 256 thr, per-thread 4x8.
// tx = tid&7 -> 8 cols (tx*8); ty = tid>>3 -> 4 rows (ty*4).
// ---------------------------------------------------------------------------
__global__ __launch_bounds__(256)
void gemm1_kernel(const float* __restrict__ X,
                  const float* __restrict__ W, int N) {
    __shared__ float xs[128 * PA];   // [r][k], row-major
    __shared__ float ws[KCH * PW];   // [k][c]
    const int tid = threadIdx.x;
    const int tx = tid & 7;
    const int ty = tid >> 3;
    const int row0 = blockIdx.x * 128;
    const int col0 = blockIdx.y * 64;

    float acc[4][8];
#pragma unroll
    for (int i = 0; i < 4; i++)
#pragma unroll
        for (int j = 0; j < 8; j++) acc[i][j] = 0.f;

    for (int kc = 0; kc < F_IN; kc += KCH) {
        // A fill: 128 rows x 32 k = 1024 float4 (4/thread), coalesced
#pragma unroll
        for (int it = 0; it < 4; it++) {
            int idx = tid + it * 256;
            int r = idx >> 3;
            int c4 = idx & 7;
            int gr = row0 + r;
            float4 v = make_float4(0.f, 0.f, 0.f, 0.f);
            if (gr < N)
                v = *reinterpret_cast<const float4*>(&X[(size_t)gr * F_IN + kc + c4 * 4]);
            *reinterpret_cast<float4*>(&xs[r * PA + c4 * 4]) = v;
        }
        // W fill: 32 k x 64 cols = 512 float4 (2/thread)
#pragma unroll
        for (int it = 0; it < 2; it++) {
            int idx = tid + it * 256;
            int rk = idx >> 4;
            int c4 = idx & 15;
            float4 v = *reinterpret_cast<const float4*>(
                &W[(size_t)(kc + rk) * F_MID + col0 + c4 * 4]);
            *reinterpret_cast<float4*>(&ws[rk * PW + c4 * 4]) = v;
        }
        __syncthreads();
#pragma unroll 8
        for (int k = 0; k < KCH; k++) {
            float a0 = xs[(ty * 4 + 0) * PA + k];
            float a1 = xs[(ty * 4 + 1) * PA + k];
            float a2 = xs[(ty * 4 + 2) * PA + k];
            float a3 = xs[(ty * 4 + 3) * PA + k];
            float4 w0 = *reinterpret_cast<float4*>(&ws[k * PW + tx * 8]);
            float4 w1 = *reinterpret_cast<float4*>(&ws[k * PW + tx * 8 + 4]);
            acc[0][0] += a0 * w0.x; acc[0][1] += a0 * w0.y; acc[0][2] += a0 * w0.z; acc[0][3] += a0 * w0.w;
            acc[0][4] += a0 * w1.x; acc[0][5] += a0 * w1.y; acc[0][6] += a0 * w1.z; acc[0][7] += a0 * w1.w;
            acc[1][0] += a1 * w0.x; acc[1][1] += a1 * w0.y; acc[1][2] += a1 * w0.z; acc[1][3] += a1 * w0.w;
            acc[1][4] += a1 * w1.x; acc[1][5] += a1 * w1.y; acc[1][6] += a1 * w1.z; acc[1][7] += a1 * w1.w;
            acc[2][0] += a2 * w0.x; acc[2][1] += a2 * w0.y; acc[2][2] += a2 * w0.z; acc[2][3] += a2 * w0.w;
            acc[2][4] += a2 * w1.x; acc[2][5] += a2 * w1.y; acc[2][6] += a2 * w1.z; acc[2][7] += a2 * w1.w;
            acc[3][0] += a3 * w0.x; acc[3][1] += a3 * w0.y; acc[3][2] += a3 * w0.z; acc[3][3] += a3 * w0.w;
            acc[3][4] += a3 * w1.x; acc[3][5] += a3 * w1.y; acc[3][6] += a3 * w1.z; acc[3][7] += a3 * w1.w;
        }
        __syncthreads();
    }
    // epilogue: fp16 mirror only
#pragma unroll
    for (int i = 0; i < 4; i++) {
        int gr = row0 + ty * 4 + i;
        if (gr < N) {
            size_t base = (size_t)gr * F_MID + col0 + tx * 8;
            *reinterpret_cast<__half2*>(&g_h1h[base + 0]) = __floats2half2_rn(acc[i][0], acc[i][1]);
            *reinterpret_cast<__half2*>(&g_h1h[base + 2]) = __floats2half2_rn(acc[i][2], acc[i][3]);
            *reinterpret_cast<__half2*>(&g_h1h[base + 4]) = __floats2half2_rn(acc[i][4], acc[i][5]);
            *reinterpret_cast<__half2*>(&g_h1h[base + 6]) = __floats2half2_rn(acc[i][6], acc[i][7]);
        }
    }
}

// ---------------------------------------------------------------------------
// GEMM2: h2h = fp16(a1 @ W2). Same structure, 64 output cols.
// ---------------------------------------------------------------------------
__global__ __launch_bounds__(256)
void gemm2_kernel(const float* __restrict__ W, int N) {
    __shared__ float xs[128 * PA];
    __shared__ float ws[KCH * PW];
    const int tid = threadIdx.x;
    const int tx = tid & 7;
    const int ty = tid >> 3;
    const int row0 = blockIdx.x * 128;

    float acc[4][8];
#pragma unroll
    for (int i = 0; i < 4; i++)
#pragma unroll
        for (int j = 0; j < 8; j++) acc[i][j] = 0.f;

    for (int kc = 0; kc < F_MID; kc += KCH) {
#pragma unroll
        for (int it = 0; it < 4; it++) {
            int idx = tid + it * 256;
            int r = idx >> 3;
            int c4 = idx & 7;
            int gr = row0 + r;
            float4 v = make_float4(0.f, 0.f, 0.f, 0.f);
            if (gr < N)
                v = *reinterpret_cast<const float4*>(&g_a1[(size_t)gr * F_MID + kc + c4 * 4]);
            *reinterpret_cast<float4*>(&xs[r * PA + c4 * 4]) = v;
        }
#pragma unroll
        for (int it = 0; it < 2; it++) {
            int idx = tid + it * 256;
            int rk = idx >> 4;
            int c4 = idx & 15;
            float4 v = *reinterpret_cast<const float4*>(
                &W[(size_t)(kc + rk) * F_OUT + c4 * 4]);
            *reinterpret_cast<float4*>(&ws[rk * PW + c4 * 4]) = v;
        }
        __syncthreads();
#pragma unroll 8
        for (int k = 0; k < KCH; k++) {
            float a0 = xs[(ty * 4 + 0) * PA + k];
            float a1 = xs[(ty * 4 + 1) * PA + k];
            float a2 = xs[(ty * 4 + 2) * PA + k];
            float a3 = xs[(ty * 4 + 3) * PA + k];
            float4 w0 = *reinterpret_cast<float4*>(&ws[k * PW + tx * 8]);
            float4 w1 = *reinterpret_cast<float4*>(&ws[k * PW + tx * 8 + 4]);
            acc[0][0] += a0 * w0.x; acc[0][1] += a0 * w0.y; acc[0][2] += a0 * w0.z; acc[0][3] += a0 * w0.w;
            acc[0][4] += a0 * w1.x; acc[0][5] += a0 * w1.y; acc[0][6] += a0 * w1.z; acc[0][7] += a0 * w1.w;
            acc[1][0] += a1 * w0.x; acc[1][1] += a1 * w0.y; acc[1][2] += a1 * w0.z; acc[1][3] += a1 * w0.w;
            acc[1][4] += a1 * w1.x; acc[1][5] += a1 * w1.y; acc[1][6] += a1 * w1.z; acc[1][7] += a1 * w1.w;
            acc[2][0] += a2 * w0.x; acc[2][1] += a2 * w0.y; acc[2][2] += a2 * w0.z; acc[2][3] += a2 * w0.w;
            acc[2][4] += a2 * w1.x; acc[2][5] += a2 * w1.y; acc[2][6] += a2 * w1.z; acc[2][7] += a2 * w1.w;
            acc[3][0] += a3 * w0.x; acc[3][1] += a3 * w0.y; acc[3][2] += a3 * w0.z; acc[3][3] += a3 * w0.w;
            acc[3][4] += a3 * w1.x; acc[3][5] += a3 * w1.y; acc[3][6] += a3 * w1.z; acc[3][7] += a3 * w1.w;
        }
        __syncthreads();
    }
#pragma unroll
    for (int i = 0; i < 4; i++) {
        int gr = row0 + ty * 4 + i;
        if (gr < N) {
            size_t base = (size_t)gr * F_OUT + tx * 8;
            *reinterpret_cast<__half2*>(&g_h2h[base + 0]) = __floats2half2_rn(acc[i][0], acc[i][1]);
            *reinterpret_cast<__half2*>(&g_h2h[base + 2]) = __floats2half2_rn(acc[i][2], acc[i][3]);
            *reinterpret_cast<__half2*>(&g_h2h[base + 4]) = __floats2half2_rn(acc[i][4], acc[i][5]);
            *reinterpret_cast<__half2*>(&g_h2h[base + 6]) = __floats2half2_rn(acc[i][6], acc[i][7]);
        }
    }
}

// ---------------------------------------------------------------------------
// scan (3 phases)
// ---------------------------------------------------------------------------
__global__ void scan_local_kernel(int N) {
    __shared__ int sh[SCAN_CHUNK];
    int tid = threadIdx.x;
    int gi = blockIdx.x * SCAN_CHUNK + tid;
    int v = (gi < N) ? g_deg[gi] : 0;
    sh[tid] = v;
    __syncthreads();
    for (int off = 1; off < SCAN_CHUNK; off <<= 1) {
        int t = 0;
        if (tid >= off) t = sh[tid - off];
        __syncthreads();
        if (tid >= off) sh[tid] += t;
        __syncthreads();
    }
    if (gi < N) g_rowptr[gi] = sh[tid] - v;
    if (tid == SCAN_CHUNK - 1) g_bsum[blockIdx.x] = sh[tid];
}

__global__ void scan_bsum_kernel(int nblk, int N) {
    __shared__ int sh[128];
    int tid = threadIdx.x;
    int v = (tid < nblk) ? g_bsum[tid] : 0;
    sh[tid] = v;
    __syncthreads();
    for (int off = 1; off < 128; off <<= 1) {
        int t = 0;
        if (tid >= off) t = sh[tid - off];
        __syncthreads();
        if (tid >= off) sh[tid] += t;
        __syncthreads();
    }
    if (tid < nblk) g_boff[tid] = sh[tid] - v;
    if (tid == 127) g_rowptr[N] = sh[127];
}

__global__ void scan_finalize_kernel(int N) {
    int gi = blockIdx.x * blockDim.x + threadIdx.x;
    if (gi < N) {
        int rp = g_rowptr[gi] + g_boff[gi / SCAN_CHUNK];
        g_rowptr[gi] = rp;
        g_cursor[gi] = rp;
        g_dinv[gi] = rsqrtf((float)(g_deg[gi] + 1));
    }
}

__global__ void csr_fill_kernel(int E) {
    int stride = gridDim.x * blockDim.x;
    for (int e = blockIdx.x * blockDim.x + threadIdx.x; e < E; e += stride) {
        int d = g_dst[e];
        int pos = atomicAdd(&g_cursor[d], 1);
        g_csrc[pos] = g_src[e];
    }
}

// ---------------------------------------------------------------------------
// agg1: warp per dst row; gathers fp16 h1, fp32 accumulate; fused bias+relu.
// lane covers cols lane*4 .. lane*4+3 (two half2 loads per row).
// ---------------------------------------------------------------------------
__global__ void agg1_kernel(const float* __restrict__ b1, int N) {
    int lane = threadIdx.x & 31;
    int warp = (blockIdx.x * blockDim.x + threadIdx.x) >> 5;
    int nwarps = (gridDim.x * blockDim.x) >> 5;
    float4 bb = *reinterpret_cast<const float4*>(&b1[lane * 4]);
    for (int r = warp; r < N; r += nwarps) {
        float dr = g_dinv[r];
        float d2 = dr * dr;
        size_t rbase = (size_t)r * F_MID + lane * 4;
        __half2 sa = *reinterpret_cast<const __half2*>(&g_h1h[rbase]);
        __half2 sb = *reinterpret_cast<const __half2*>(&g_h1h[rbase + 2]);
        float2 f0 = __half22float2(sa);
        float2 f1 = __half22float2(sb);
        float ax = f0.x * d2, ay = f0.y * d2, az = f1.x * d2, aw = f1.y * d2;

        int beg = g_rowptr[r];
        int end = g_rowptr[r + 1];
        int e = beg;
        for (; e + 1 < end; e += 2) {
            int s0 = g_csrc[e];
            int s1 = g_csrc[e + 1];
            float n0 = g_dinv[s0] * dr;
            float n1 = g_dinv[s1] * dr;
            size_t b0 = (size_t)s0 * F_MID + lane * 4;
            size_t b1o = (size_t)s1 * F_MID + lane * 4;
            __half2 p0 = *reinterpret_cast<const __half2*>(&g_h1h[b0]);
            __half2 p1 = *reinterpret_cast<const __half2*>(&g_h1h[b0 + 2]);
            __half2 q0 = *reinterpret_cast<const __half2*>(&g_h1h[b1o]);
            __half2 q1 = *reinterpret_cast<const __half2*>(&g_h1h[b1o + 2]);
            float2 pa = __half22float2(p0), pb = __half22float2(p1);
            float2 qa = __half22float2(q0), qb = __half22float2(q1);
            ax += pa.x * n0 + qa.x * n1;
            ay += pa.y * n0 + qa.y * n1;
            az += pb.x * n0 + qb.x * n1;
            aw += pb.y * n0 + qb.y * n1;
        }
        if (e < end) {
            int s0 = g_csrc[e];
            float n0 = g_dinv[s0] * dr;
            size_t b0 = (size_t)s0 * F_MID + lane * 4;
            __half2 p0 = *reinterpret_cast<const __half2*>(&g_h1h[b0]);
            __half2 p1 = *reinterpret_cast<const __half2*>(&g_h1h[b0 + 2]);
            float2 pa = __half22float2(p0), pb = __half22float2(p1);
            ax += pa.x * n0;
            ay += pa.y * n0;
            az += pb.x * n0;
            aw += pb.y * n0;
        }
        float4 outv;
        outv.x = fmaxf(ax + bb.x, 0.f);
        outv.y = fmaxf(ay + bb.y, 0.f);
        outv.z = fmaxf(az + bb.z, 0.f);
        outv.w = fmaxf(aw + bb.w, 0.f);
        *reinterpret_cast<float4*>(&g_a1[rbase]) = outv;
    }
}

// ---------------------------------------------------------------------------
// agg2: warp per dst row; gathers fp16 h2; fused bias+log_softmax -> out.
// lane covers cols lane*2, lane*2+1 (one half2 per row).
// ---------------------------------------------------------------------------
__global__ void agg2_kernel(const float* __restrict__ b2,
                            float* __restrict__ out, int N) {
    int lane = threadIdx.x & 31;
    int warp = (blockIdx.x * blockDim.x + threadIdx.x) >> 5;
    int nwarps = (gridDim.x * blockDim.x) >> 5;
    float2 bb = *reinterpret_cast<const float2*>(&b2[lane * 2]);
    for (int r = warp; r < N; r += nwarps) {
        float dr = g_dinv[r];
        float d2 = dr * dr;
        size_t rbase = (size_t)r * F_OUT + lane * 2;
        float2 f = __half22float2(*reinterpret_cast<const __half2*>(&g_h2h[rbase]));
        float ax = f.x * d2, ay = f.y * d2;

        int beg = g_rowptr[r];
        int end = g_rowptr[r + 1];
        int e = beg;
        for (; e + 1 < end; e += 2) {
            int s0 = g_csrc[e];
            int s1 = g_csrc[e + 1];
            float n0 = g_dinv[s0] * dr;
            float n1 = g_dinv[s1] * dr;
            float2 p = __half22float2(
                *reinterpret_cast<const __half2*>(&g_h2h[(size_t)s0 * F_OUT + lane * 2]));
            float2 q = __half22float2(
                *reinterpret_cast<const __half2*>(&g_h2h[(size_t)s1 * F_OUT + lane * 2]));
            ax += p.x * n0 + q.x * n1;
            ay += p.y * n0 + q.y * n1;
        }
        if (e < end) {
            int s0 = g_csrc[e];
            float n0 = g_dinv[s0] * dr;
            float2 p = __half22float2(
                *reinterpret_cast<const __half2*>(&g_h2h[(size_t)s0 * F_OUT + lane * 2]));
            ax += p.x * n0;
            ay += p.y * n0;
        }
        float vx = ax + bb.x;
        float vy = ay + bb.y;
        float m = fmaxf(vx, vy);
#pragma unroll
        for (int o = 16; o; o >>= 1) m = fmaxf(m, __shfl_xor_sync(0xffffffffu, m, o));
        float s = __expf(vx - m) + __expf(vy - m);
#pragma unroll
        for (int o = 16; o; o >>= 1) s += __shfl_xor_sync(0xffffffffu, s, o);
        float lse = m + __logf(s);
        *reinterpret_cast<float2*>(&out[rbase]) = make_float2(vx - lse, vy - lse);
    }
}

// ---------------------------------------------------------------------------
extern "C" void kernel_launch(void* const* d_in, const int* in_sizes, int n_in,
                              void* d_out, int out_size) {
    const float* x  = (const float*)d_in[0];
    const void*  ei = d_in[1];
    const float* W1 = (const float*)d_in[2];
    const float* b1 = (const float*)d_in[3];
    const float* W2 = (const float*)d_in[4];
    const float* b2 = (const float*)d_in[5];
    float* out = (float*)d_out;

    int N = in_sizes[0] / F_IN;     // 100000
    int E = in_sizes[1] / 2;        // 1600000
    if (N > NMAX) N = NMAX;
    if (E > EMAX) E = EMAX;

    int nblk_scan = (N + SCAN_CHUNK - 1) / SCAN_CHUNK;
    int grows = (N + 127) / 128;

    detect_kernel<<<1, 32>>>((const int*)ei);
    zero_deg_kernel<<<(N + 255) / 256, 256>>>(N);
    edge_prep_kernel<<<2048, 256>>>(ei, E, N);
    gemm1_kernel<<<dim3(grows, 2), 256>>>(x, W1, N);   // #4: ncu slot
    scan_local_kernel<<<nblk_scan, SCAN_CHUNK>>>(N);
    scan_bsum_kernel<<<1, 128>>>(nblk_scan, N);
    scan_finalize_kernel<<<(N + 255) / 256, 256>>>(N);
    csr_fill_kernel<<<2048, 256>>>(E);
    agg1_kernel<<<(N * 32 + 255) / 256, 256>>>(b1, N);
    gemm2_kernel<<<grows, 256>>>(W2, N);
    agg2_kernel<<<(N * 32 + 255) / 256, 256>>>(b2, out, N);
}

// round 15
// speedup vs baseline: 1.1458x; 1.1458x over previous
#include <cuda_runtime.h>
#include <cuda_fp16.h>
#include <cstdint>

// ---------------------------------------------------------------------------
// SimpleGCN R14 = R12's proven GEMM shape (64x64 tile, acc[4][4], transposed-A
// smem, 56 regs, 96us) + R13's proven fp16 h1/h2 mirrors (rel_err 3.2e-6,
// halves the LTS-bound agg gather traffic).
// R13 post-mortem: 4x8 tile regressed (L1 still 90%, occ down) -> GEMM shape
// frozen at the R12 local optimum; wins composed instead.
// ---------------------------------------------------------------------------

#define NMAX 100000
#define EMAX 1600000
#define F_IN 128
#define F_MID 128
#define F_OUT 64

#define SCAN_CHUNK 1024
#define NBLK_SCAN ((NMAX + SCAN_CHUNK - 1) / SCAN_CHUNK)

#define TP 68   // transposed-tile pitch: 64 + 4

__device__ __align__(16) int    g_src[EMAX];
__device__ __align__(16) int    g_dst[EMAX];
__device__ __align__(16) int    g_csrc[EMAX];
__device__ __align__(16) int    g_deg[NMAX];
__device__ __align__(16) int    g_rowptr[NMAX + 1];
__device__ __align__(16) int    g_cursor[NMAX];
__device__ __align__(16) int    g_bsum[NBLK_SCAN];
__device__ __align__(16) int    g_boff[NBLK_SCAN];
__device__ __align__(16) float  g_dinv[NMAX];
__device__ __align__(16) __half g_h1h[(size_t)NMAX * F_MID];  // fp16(x@W1)
__device__ __align__(16) float  g_a1[(size_t)NMAX * F_MID];   // relu(agg+b1)
__device__ __align__(16) __half g_h2h[(size_t)NMAX * F_OUT];  // fp16(a1@W2)
__device__ int g_is64;

// ---------------------------------------------------------------------------
__global__ void detect_kernel(const int* __restrict__ ei32) {
    if (threadIdx.x == 0 && blockIdx.x == 0) {
        int allzero = 1;
        for (int i = 0; i < 64; i++)
            if (ei32[2 * i + 1] != 0) { allzero = 0; break; }
        g_is64 = allzero;
    }
}

__global__ void zero_deg_kernel(int N) {
    int i = blockIdx.x * blockDim.x + threadIdx.x;
    if (i < N) g_deg[i] = 0;
}

__global__ void edge_prep_kernel(const void* __restrict__ ei_raw, int E, int N) {
    const int is64 = g_is64;
    const int stride = gridDim.x * blockDim.x;
    const int* __restrict__ p32 = (const int*)ei_raw;
    const long long* __restrict__ p64 = (const long long*)ei_raw;
    for (int e = blockIdx.x * blockDim.x + threadIdx.x; e < E; e += stride) {
        int s, d;
        if (is64) {
            s = (int)p64[e];
            d = (int)p64[(size_t)E + e];
        } else {
            s = p32[e];
            d = p32[(size_t)E + e];
        }
        s = min(max(s, 0), N - 1);
        d = min(max(d, 0), N - 1);
        g_src[e] = s;
        g_dst[e] = d;
        atomicAdd(&g_deg[d], 1);
    }
}

// ---------------------------------------------------------------------------
// GEMM1: g_h1h = fp16(x @ W1). 64x64 tile, 256 threads, acc[4][4],
// transposed-A smem (xs[k][r]) -> broadcast LDS.128.
// ---------------------------------------------------------------------------
__global__ void gemm1_kernel(const float* __restrict__ X,
                             const float* __restrict__ W, int N) {
    __shared__ float xs[64 * TP];   // [k][r]
    __shared__ float ws[64 * TP];   // [k][c]
    int tid = threadIdx.x;
    int tx = tid & 15;
    int ty = tid >> 4;
    int row0 = blockIdx.x * 64;
    int col0 = blockIdx.y * 64;

    float acc[4][4];
#pragma unroll
    for (int i = 0; i < 4; i++)
#pragma unroll
        for (int j = 0; j < 4; j++) acc[i][j] = 0.f;

    for (int k0 = 0; k0 < F_IN; k0 += 64) {
#pragma unroll
        for (int it = 0; it < 4; it++) {
            int r = (tid >> 2) & 63;
            int c4 = 4 * it + (tid & 3);
            int gr = row0 + r;
            float4 v = make_float4(0.f, 0.f, 0.f, 0.f);
            if (gr < N)
                v = *reinterpret_cast<const float4*>(&X[(size_t)gr * F_IN + k0 + c4 * 4]);
            xs[(c4 * 4 + 0) * TP + r] = v.x;
            xs[(c4 * 4 + 1) * TP + r] = v.y;
            xs[(c4 * 4 + 2) * TP + r] = v.z;
            xs[(c4 * 4 + 3) * TP + r] = v.w;
        }
#pragma unroll
        for (int it = 0; it < 4; it++) {
            int t = tid + it * 256;
            int rk = t >> 4;
            int c4 = t & 15;
            float4 v = *reinterpret_cast<const float4*>(&W[(size_t)(k0 + rk) * F_MID + col0 + c4 * 4]);
            *reinterpret_cast<float4*>(&ws[rk * TP + c4 * 4]) = v;
        }
        __syncthreads();
#pragma unroll 16
        for (int k = 0; k < 64; k++) {
            float4 a = *reinterpret_cast<float4*>(&xs[k * TP + ty * 4]);
            float4 w = *reinterpret_cast<float4*>(&ws[k * TP + tx * 4]);
            acc[0][0] += a.x * w.x; acc[0][1] += a.x * w.y; acc[0][2] += a.x * w.z; acc[0][3] += a.x * w.w;
            acc[1][0] += a.y * w.x; acc[1][1] += a.y * w.y; acc[1][2] += a.y * w.z; acc[1][3] += a.y * w.w;
            acc[2][0] += a.z * w.x; acc[2][1] += a.z * w.y; acc[2][2] += a.z * w.z; acc[2][3] += a.z * w.w;
            acc[3][0] += a.w * w.x; acc[3][1] += a.w * w.y; acc[3][2] += a.w * w.z; acc[3][3] += a.w * w.w;
        }
        __syncthreads();
    }
#pragma unroll
    for (int i = 0; i < 4; i++) {
        int gr = row0 + ty * 4 + i;
        if (gr < N) {
            size_t base = (size_t)gr * F_MID + col0 + tx * 4;
            *reinterpret_cast<__half2*>(&g_h1h[base + 0]) = __floats2half2_rn(acc[i][0], acc[i][1]);
            *reinterpret_cast<__half2*>(&g_h1h[base + 2]) = __floats2half2_rn(acc[i][2], acc[i][3]);
        }
    }
}

// ---------------------------------------------------------------------------
// GEMM2: g_h2h = fp16(g_a1 @ W2). Same structure, 64 cols.
// ---------------------------------------------------------------------------
__global__ void gemm2_kernel(const float* __restrict__ W, int N) {
    __shared__ float xs[64 * TP];
    __shared__ float ws[64 * TP];
    int tid = threadIdx.x;
    int tx = tid & 15;
    int ty = tid >> 4;
    int row0 = blockIdx.x * 64;

    float acc[4][4];
#pragma unroll
    for (int i = 0; i < 4; i++)
#pragma unroll
        for (int j = 0; j < 4; j++) acc[i][j] = 0.f;

    for (int k0 = 0; k0 < F_MID; k0 += 64) {
#pragma unroll
        for (int it = 0; it < 4; it++) {
            int r = (tid >> 2) & 63;
            int c4 = 4 * it + (tid & 3);
            int gr = row0 + r;
            float4 v = make_float4(0.f, 0.f, 0.f, 0.f);
            if (gr < N)
                v = *reinterpret_cast<const float4*>(&g_a1[(size_t)gr * F_MID + k0 + c4 * 4]);
            xs[(c4 * 4 + 0) * TP + r] = v.x;
            xs[(c4 * 4 + 1) * TP + r] = v.y;
            xs[(c4 * 4 + 2) * TP + r] = v.z;
            xs[(c4 * 4 + 3) * TP + r] = v.w;
        }
#pragma unroll
        for (int it = 0; it < 4; it++) {
            int t = tid + it * 256;
            int rk = t >> 4;
            int c4 = t & 15;
            float4 v = *reinterpret_cast<const float4*>(&W[(size_t)(k0 + rk) * F_OUT + c4 * 4]);
            *reinterpret_cast<float4*>(&ws[rk * TP + c4 * 4]) = v;
        }
        __syncthreads();
#pragma unroll 16
        for (int k = 0; k < 64; k++) {
            float4 a = *reinterpret_cast<float4*>(&xs[k * TP + ty * 4]);
            float4 w = *reinterpret_cast<float4*>(&ws[k * TP + tx * 4]);
            acc[0][0] += a.x * w.x; acc[0][1] += a.x * w.y; acc[0][2] += a.x * w.z; acc[0][3] += a.x * w.w;
            acc[1][0] += a.y * w.x; acc[1][1] += a.y * w.y; acc[1][2] += a.y * w.z; acc[1][3] += a.y * w.w;
            acc[2][0] += a.z * w.x; acc[2][1] += a.z * w.y; acc[2][2] += a.z * w.z; acc[2][3] += a.z * w.w;
            acc[3][0] += a.w * w.x; acc[3][1] += a.w * w.y; acc[3][2] += a.w * w.z; acc[3][3] += a.w * w.w;
        }
        __syncthreads();
    }
#pragma unroll
    for (int i = 0; i < 4; i++) {
        int gr = row0 + ty * 4 + i;
        if (gr < N) {
            size_t base = (size_t)gr * F_OUT + tx * 4;
            *reinterpret_cast<__half2*>(&g_h2h[base + 0]) = __floats2half2_rn(acc[i][0], acc[i][1]);
            *reinterpret_cast<__half2*>(&g_h2h[base + 2]) = __floats2half2_rn(acc[i][2], acc[i][3]);
        }
    }
}

// ---------------------------------------------------------------------------
// scan (3 phases)
// ---------------------------------------------------------------------------
__global__ void scan_local_kernel(int N) {
    __shared__ int sh[SCAN_CHUNK];
    int tid = threadIdx.x;
    int gi = blockIdx.x * SCAN_CHUNK + tid;
    int v = (gi < N) ? g_deg[gi] : 0;
    sh[tid] = v;
    __syncthreads();
    for (int off = 1; off < SCAN_CHUNK; off <<= 1) {
        int t = 0;
        if (tid >= off) t = sh[tid - off];
        __syncthreads();
        if (tid >= off) sh[tid] += t;
        __syncthreads();
    }
    if (gi < N) g_rowptr[gi] = sh[tid] - v;
    if (tid == SCAN_CHUNK - 1) g_bsum[blockIdx.x] = sh[tid];
}

__global__ void scan_bsum_kernel(int nblk, int N) {
    __shared__ int sh[128];
    int tid = threadIdx.x;
    int v = (tid < nblk) ? g_bsum[tid] : 0;
    sh[tid] = v;
    __syncthreads();
    for (int off = 1; off < 128; off <<= 1) {
        int t = 0;
        if (tid >= off) t = sh[tid - off];
        __syncthreads();
        if (tid >= off) sh[tid] += t;
        __syncthreads();
    }
    if (tid < nblk) g_boff[tid] = sh[tid] - v;
    if (tid == 127) g_rowptr[N] = sh[127];
}

__global__ void scan_finalize_kernel(int N) {
    int gi = blockIdx.x * blockDim.x + threadIdx.x;
    if (gi < N) {
        int rp = g_rowptr[gi] + g_boff[gi / SCAN_CHUNK];
        g_rowptr[gi] = rp;
        g_cursor[gi] = rp;
        g_dinv[gi] = rsqrtf((float)(g_deg[gi] + 1));
    }
}

__global__ void csr_fill_kernel(int E) {
    int stride = gridDim.x * blockDim.x;
    for (int e = blockIdx.x * blockDim.x + threadIdx.x; e < E; e += stride) {
        int d = g_dst[e];
        int pos = atomicAdd(&g_cursor[d], 1);
        g_csrc[pos] = g_src[e];
    }
}

// ---------------------------------------------------------------------------
// agg1: warp per dst row; gathers fp16 h1, fp32 accumulate; fused bias+relu.
// ---------------------------------------------------------------------------
__global__ void agg1_kernel(const float* __restrict__ b1, int N) {
    int lane = threadIdx.x & 31;
    int warp = (blockIdx.x * blockDim.x + threadIdx.x) >> 5;
    int nwarps = (gridDim.x * blockDim.x) >> 5;
    float4 bb = *reinterpret_cast<const float4*>(&b1[lane * 4]);
    for (int r = warp; r < N; r += nwarps) {
        float dr = g_dinv[r];
        float d2 = dr * dr;
        size_t rbase = (size_t)r * F_MID + lane * 4;
        __half2 sa = *reinterpret_cast<const __half2*>(&g_h1h[rbase]);
        __half2 sb = *reinterpret_cast<const __half2*>(&g_h1h[rbase + 2]);
        float2 f0 = __half22float2(sa);
        float2 f1 = __half22float2(sb);
        float ax = f0.x * d2, ay = f0.y * d2, az = f1.x * d2, aw = f1.y * d2;

        int beg = g_rowptr[r];
        int end = g_rowptr[r + 1];
        int e = beg;
        for (; e + 1 < end; e += 2) {
            int s0 = g_csrc[e];
            int s1 = g_csrc[e + 1];
            float n0 = g_dinv[s0] * dr;
            float n1 = g_dinv[s1] * dr;
            size_t b0 = (size_t)s0 * F_MID + lane * 4;
            size_t b1o = (size_t)s1 * F_MID + lane * 4;
            __half2 p0 = *reinterpret_cast<const __half2*>(&g_h1h[b0]);
            __half2 p1 = *reinterpret_cast<const __half2*>(&g_h1h[b0 + 2]);
            __half2 q0 = *reinterpret_cast<const __half2*>(&g_h1h[b1o]);
            __half2 q1 = *reinterpret_cast<const __half2*>(&g_h1h[b1o + 2]);
            float2 pa = __half22float2(p0), pb = __half22float2(p1);
            float2 qa = __half22float2(q0), qb = __half22float2(q1);
            ax += pa.x * n0 + qa.x * n1;
            ay += pa.y * n0 + qa.y * n1;
            az += pb.x * n0 + qb.x * n1;
            aw += pb.y * n0 + qb.y * n1;
        }
        if (e < end) {
            int s0 = g_csrc[e];
            float n0 = g_dinv[s0] * dr;
            size_t b0 = (size_t)s0 * F_MID + lane * 4;
            __half2 p0 = *reinterpret_cast<const __half2*>(&g_h1h[b0]);
            __half2 p1 = *reinterpret_cast<const __half2*>(&g_h1h[b0 + 2]);
            float2 pa = __half22float2(p0), pb = __half22float2(p1);
            ax += pa.x * n0;
            ay += pa.y * n0;
            az += pb.x * n0;
            aw += pb.y * n0;
        }
        float4 outv;
        outv.x = fmaxf(ax + bb.x, 0.f);
        outv.y = fmaxf(ay + bb.y, 0.f);
        outv.z = fmaxf(az + bb.z, 0.f);
        outv.w = fmaxf(aw + bb.w, 0.f);
        *reinterpret_cast<float4*>(&g_a1[rbase]) = outv;
    }
}

// ---------------------------------------------------------------------------
// agg2: warp per dst row; gathers fp16 h2; fused bias+log_softmax -> out.
// ---------------------------------------------------------------------------
__global__ void agg2_kernel(const float* __restrict__ b2,
                            float* __restrict__ out, int N) {
    int lane = threadIdx.x & 31;
    int warp = (blockIdx.x * blockDim.x + threadIdx.x) >> 5;
    int nwarps = (gridDim.x * blockDim.x) >> 5;
    float2 bb = *reinterpret_cast<const float2*>(&b2[lane * 2]);
    for (int r = warp; r < N; r += nwarps) {
        float dr = g_dinv[r];
        float d2 = dr * dr;
        size_t rbase = (size_t)r * F_OUT + lane * 2;
        float2 f = __half22float2(*reinterpret_cast<const __half2*>(&g_h2h[rbase]));
        float ax = f.x * d2, ay = f.y * d2;

        int beg = g_rowptr[r];
        int end = g_rowptr[r + 1];
        int e = beg;
        for (; e + 1 < end; e += 2) {
            int s0 = g_csrc[e];
            int s1 = g_csrc[e + 1];
            float n0 = g_dinv[s0] * dr;
            float n1 = g_dinv[s1] * dr;
            float2 p = __half22float2(
                *reinterpret_cast<const __half2*>(&g_h2h[(size_t)s0 * F_OUT + lane * 2]));
            float2 q = __half22float2(
                *reinterpret_cast<const __half2*>(&g_h2h[(size_t)s1 * F_OUT + lane * 2]));
            ax += p.x * n0 + q.x * n1;
            ay += p.y * n0 + q.y * n1;
        }
        if (e < end) {
            int s0 = g_csrc[e];
            float n0 = g_dinv[s0] * dr;
            float2 p = __half22float2(
                *reinterpret_cast<const __half2*>(&g_h2h[(size_t)s0 * F_OUT + lane * 2]));
            ax += p.x * n0;
            ay += p.y * n0;
        }
        float vx = ax + bb.x;
        float vy = ay + bb.y;
        float m = fmaxf(vx, vy);
#pragma unroll
        for (int o = 16; o; o >>= 1) m = fmaxf(m, __shfl_xor_sync(0xffffffffu, m, o));
        float s = __expf(vx - m) + __expf(vy - m);
#pragma unroll
        for (int o = 16; o; o >>= 1) s += __shfl_xor_sync(0xffffffffu, s, o);
        float lse = m + __logf(s);
        *reinterpret_cast<float2*>(&out[rbase]) = make_float2(vx - lse, vy - lse);
    }
}

// ---------------------------------------------------------------------------
extern "C" void kernel_launch(void* const* d_in, const int* in_sizes, int n_in,
                              void* d_out, int out_size) {
    const float* x  = (const float*)d_in[0];
    const void*  ei = d_in[1];
    const float* W1 = (const float*)d_in[2];
    const float* b1 = (const float*)d_in[3];
    const float* W2 = (const float*)d_in[4];
    const float* b2 = (const float*)d_in[5];
    float* out = (float*)d_out;

    int N = in_sizes[0] / F_IN;     // 100000
    int E = in_sizes[1] / 2;        // 1600000
    if (N > NMAX) N = NMAX;
    if (E > EMAX) E = EMAX;

    int nblk_scan = (N + SCAN_CHUNK - 1) / SCAN_CHUNK;

    detect_kernel<<<1, 32>>>((const int*)ei);
    zero_deg_kernel<<<(N + 255) / 256, 256>>>(N);
    edge_prep_kernel<<<2048, 256>>>(ei, E, N);
    gemm1_kernel<<<dim3((N + 63) / 64, 2), 256>>>(x, W1, N);   // #4: ncu slot
    scan_local_kernel<<<nblk_scan, SCAN_CHUNK>>>(N);
    scan_bsum_kernel<<<1, 128>>>(nblk_scan, N);
    scan_finalize_kernel<<<(N + 255) / 256, 256>>>(N);
    csr_fill_kernel<<<2048, 256>>>(E);
    agg1_kernel<<<(N * 32 + 255) / 256, 256>>>(b1, N);
    gemm2_kernel<<<(N + 63) / 64, 256>>>(W2, N);
    agg2_kernel<<<(N * 32 + 255) / 256, 256>>>(b2, out, N);
}

// round 16
// speedup vs baseline: 1.4883x; 1.2989x over previous
#include <cuda_runtime.h>
#include <cuda_fp16.h>
#include <cstdint>

// ---------------------------------------------------------------------------
// SimpleGCN R15: fp16 tensor-core GEMMs (mma.sync.m16n8k16, fp32 accum) in
// NON-TEMPLATE kernels engineered for zero local memory (the R6-R11 failures
// are attributed to nonzero lmem spill -> fixed 128MiB driver pool).
// Inputs quantized fp32->fp16 in the smem fill; h1/h2 mirrors already fp16
// (R13/R14 measured that quantization at rel_err 3.2e-6).
// Rest of pipeline = R14 (307us).
// ---------------------------------------------------------------------------

#define NMAX 100000
#define EMAX 1600000
#define F_IN 128
#define F_MID 128
#define F_OUT 64

#define SCAN_CHUNK 1024
#define NBLK_SCAN ((NMAX + SCAN_CHUNK - 1) / SCAN_CHUNK)

#define APH 72   // A smem pitch in halves (144 B: conflict-free frag loads)
#define WPH 72   // W smem pitch in halves

__device__ __align__(16) int    g_src[EMAX];
__device__ __align__(16) int    g_dst[EMAX];
__device__ __align__(16) int    g_csrc[EMAX];
__device__ __align__(16) int    g_deg[NMAX];
__device__ __align__(16) int    g_rowptr[NMAX + 1];
__device__ __align__(16) int    g_cursor[NMAX];
__device__ __align__(16) int    g_bsum[NBLK_SCAN];
__device__ __align__(16) int    g_boff[NBLK_SCAN];
__device__ __align__(16) float  g_dinv[NMAX];
__device__ __align__(16) __half g_h1h[(size_t)NMAX * F_MID];  // fp16(x@W1)
__device__ __align__(16) float  g_a1[(size_t)NMAX * F_MID];   // relu(agg+b1)
__device__ __align__(16) __half g_h2h[(size_t)NMAX * F_OUT];  // fp16(a1@W2)
__device__ int g_is64;

// ---------------------------------------------------------------------------
__global__ void detect_kernel(const int* __restrict__ ei32) {
    if (threadIdx.x == 0 && blockIdx.x == 0) {
        int allzero = 1;
        for (int i = 0; i < 64; i++)
            if (ei32[2 * i + 1] != 0) { allzero = 0; break; }
        g_is64 = allzero;
    }
}

__global__ void zero_deg_kernel(int N) {
    int i = blockIdx.x * blockDim.x + threadIdx.x;
    if (i < N) g_deg[i] = 0;
}

__global__ void edge_prep_kernel(const void* __restrict__ ei_raw, int E, int N) {
    const int is64 = g_is64;
    const int stride = gridDim.x * blockDim.x;
    const int* __restrict__ p32 = (const int*)ei_raw;
    const long long* __restrict__ p64 = (const long long*)ei_raw;
    for (int e = blockIdx.x * blockDim.x + threadIdx.x; e < E; e += stride) {
        int s, d;
        if (is64) {
            s = (int)p64[e];
            d = (int)p64[(size_t)E + e];
        } else {
            s = p32[e];
            d = p32[(size_t)E + e];
        }
        s = min(max(s, 0), N - 1);
        d = min(max(d, 0), N - 1);
        g_src[e] = s;
        g_dst[e] = d;
        atomicAdd(&g_deg[d], 1);
    }
}

// ---------------------------------------------------------------------------
// HMMA helpers (scalar refs only)
// ---------------------------------------------------------------------------
#define HMMA(c0, c1, c2, c3, a0, a1, a2, a3, b0, b1)                          \
    asm volatile(                                                             \
        "mma.sync.aligned.m16n8k16.row.col.f32.f16.f16.f32 "                  \
        "{%0,%1,%2,%3}, {%4,%5,%6,%7}, {%8,%9}, {%0,%1,%2,%3};"               \
        : "+f"(c0), "+f"(c1), "+f"(c2), "+f"(c3)                              \
        : "r"(a0), "r"(a1), "r"(a2), "r"(a3), "r"(b0), "r"(b1));

#define DECLC(i) float c##i##0 = 0.f, c##i##1 = 0.f, c##i##2 = 0.f, c##i##3 = 0.f;

#define MMA_STEP(i, Ws)                                                       \
    {                                                                         \
        uint32_t b0 = *reinterpret_cast<const uint32_t*>(                     \
            &Ws[((i) * 8 + g) * WPH + kb + 2 * t]);                           \
        uint32_t b1 = *reinterpret_cast<const uint32_t*>(                     \
            &Ws[((i) * 8 + g) * WPH + kb + 2 * t + 8]);                       \
        HMMA(c##i##0, c##i##1, c##i##2, c##i##3, a0, a1, a2, a3, b0, b1);     \
    }

#define EPI_STEP(i, OUT, OSTR)                                                \
    {                                                                         \
        int col = col0 + (i) * 8 + 2 * t;                                     \
        if (r0 < N)                                                           \
            *reinterpret_cast<__half2*>(&OUT[(size_t)r0 * (OSTR) + col]) =    \
                __floats2half2_rn(c##i##0, c##i##1);                          \
        if (r1 < N)                                                           \
            *reinterpret_cast<__half2*>(&OUT[(size_t)r1 * (OSTR) + col]) =    \
                __floats2half2_rn(c##i##2, c##i##3);                          \
    }

// ---------------------------------------------------------------------------
// GEMM1: g_h1h = fp16(x @ W1). Block 128x64 (grid.y = 2 col slabs),
// 8 warps, warp = 16 rows x 64 cols; fp16 smem operands, fp32 accum.
// ---------------------------------------------------------------------------
__global__ __launch_bounds__(256)
void gemm1_kernel(const float* __restrict__ X,
                  const float* __restrict__ W, int N) {
    __shared__ __align__(16) __half As[128 * APH];
    __shared__ __align__(16) __half Ws[64 * WPH];

    const int tid = threadIdx.x;
    const int lane = tid & 31;
    const int w = tid >> 5;
    const int g = lane >> 2;
    const int t = lane & 3;
    const int row0 = blockIdx.x * 128;
    const int col0 = blockIdx.y * 64;
    const int mr = w * 16 + g;

    DECLC(0) DECLC(1) DECLC(2) DECLC(3) DECLC(4) DECLC(5) DECLC(6) DECLC(7)

    for (int kc = 0; kc < F_IN; kc += 64) {
        // A fill: 128 rows x 64 k -> fp16. 2048 float4, 8/thread, coalesced.
#pragma unroll
        for (int it = 0; it < 8; it++) {
            int idx = tid + it * 256;
            int r = idx >> 4;
            int c4 = idx & 15;
            int gr = row0 + r;
            float4 v = make_float4(0.f, 0.f, 0.f, 0.f);
            if (gr < N)
                v = *reinterpret_cast<const float4*>(&X[(size_t)gr * F_IN + kc + c4 * 4]);
            *reinterpret_cast<__half2*>(&As[r * APH + c4 * 4]) = __floats2half2_rn(v.x, v.y);
            *reinterpret_cast<__half2*>(&As[r * APH + c4 * 4 + 2]) = __floats2half2_rn(v.z, v.w);
        }
        // W fill transposed: Ws[n][k]; thread covers (n, k2) -> 2 k values.
#pragma unroll
        for (int it = 0; it < 8; it++) {
            int idx = tid + it * 256;
            int k2 = idx >> 6;          // 0..31
            int n = idx & 63;
            float w0 = W[(size_t)(kc + 2 * k2) * F_MID + col0 + n];
            float w1 = W[(size_t)(kc + 2 * k2 + 1) * F_MID + col0 + n];
            *reinterpret_cast<__half2*>(&Ws[n * WPH + 2 * k2]) = __floats2half2_rn(w0, w1);
        }
        __syncthreads();

#pragma unroll
        for (int ks = 0; ks < 4; ks++) {
            const int kb = ks * 16;
            uint32_t a0 = *reinterpret_cast<const uint32_t*>(&As[mr * APH + kb + 2 * t]);
            uint32_t a1 = *reinterpret_cast<const uint32_t*>(&As[(mr + 8) * APH + kb + 2 * t]);
            uint32_t a2 = *reinterpret_cast<const uint32_t*>(&As[mr * APH + kb + 2 * t + 8]);
            uint32_t a3 = *reinterpret_cast<const uint32_t*>(&As[(mr + 8) * APH + kb + 2 * t + 8]);
            MMA_STEP(0, Ws) MMA_STEP(1, Ws) MMA_STEP(2, Ws) MMA_STEP(3, Ws)
            MMA_STEP(4, Ws) MMA_STEP(5, Ws) MMA_STEP(6, Ws) MMA_STEP(7, Ws)
        }
        __syncthreads();
    }

    const int r0 = row0 + mr;
    const int r1 = r0 + 8;
    EPI_STEP(0, g_h1h, F_MID) EPI_STEP(1, g_h1h, F_MID)
    EPI_STEP(2, g_h1h, F_MID) EPI_STEP(3, g_h1h, F_MID)
    EPI_STEP(4, g_h1h, F_MID) EPI_STEP(5, g_h1h, F_MID)
    EPI_STEP(6, g_h1h, F_MID) EPI_STEP(7, g_h1h, F_MID)
}

// ---------------------------------------------------------------------------
// GEMM2: g_h2h = fp16(g_a1 @ W2). Same structure, single 64-col slab.
// ---------------------------------------------------------------------------
__global__ __launch_bounds__(256)
void gemm2_kernel(const float* __restrict__ W, int N) {
    __shared__ __align__(16) __half As[128 * APH];
    __shared__ __align__(16) __half Ws[64 * WPH];

    const int tid = threadIdx.x;
    const int lane = tid & 31;
    const int w = tid >> 5;
    const int g = lane >> 2;
    const int t = lane & 3;
    const int row0 = blockIdx.x * 128;
    const int col0 = 0;
    const int mr = w * 16 + g;

    DECLC(0) DECLC(1) DECLC(2) DECLC(3) DECLC(4) DECLC(5) DECLC(6) DECLC(7)

    for (int kc = 0; kc < F_MID; kc += 64) {
#pragma unroll
        for (int it = 0; it < 8; it++) {
            int idx = tid + it * 256;
            int r = idx >> 4;
            int c4 = idx & 15;
            int gr = row0 + r;
            float4 v = make_float4(0.f, 0.f, 0.f, 0.f);
            if (gr < N)
                v = *reinterpret_cast<const float4*>(&g_a1[(size_t)gr * F_MID + kc + c4 * 4]);
            *reinterpret_cast<__half2*>(&As[r * APH + c4 * 4]) = __floats2half2_rn(v.x, v.y);
            *reinterpret_cast<__half2*>(&As[r * APH + c4 * 4 + 2]) = __floats2half2_rn(v.z, v.w);
        }
#pragma unroll
        for (int it = 0; it < 8; it++) {
            int idx = tid + it * 256;
            int k2 = idx >> 6;
            int n = idx & 63;
            float w0 = W[(size_t)(kc + 2 * k2) * F_OUT + n];
            float w1 = W[(size_t)(kc + 2 * k2 + 1) * F_OUT + n];
            *reinterpret_cast<__half2*>(&Ws[n * WPH + 2 * k2]) = __floats2half2_rn(w0, w1);
        }
        __syncthreads();

#pragma unroll
        for (int ks = 0; ks < 4; ks++) {
            const int kb = ks * 16;
            uint32_t a0 = *reinterpret_cast<const uint32_t*>(&As[mr * APH + kb + 2 * t]);
            uint32_t a1 = *reinterpret_cast<const uint32_t*>(&As[(mr + 8) * APH + kb + 2 * t]);
            uint32_t a2 = *reinterpret_cast<const uint32_t*>(&As[mr * APH + kb + 2 * t + 8]);
            uint32_t a3 = *reinterpret_cast<const uint32_t*>(&As[(mr + 8) * APH + kb + 2 * t + 8]);
            MMA_STEP(0, Ws) MMA_STEP(1, Ws) MMA_STEP(2, Ws) MMA_STEP(3, Ws)
            MMA_STEP(4, Ws) MMA_STEP(5, Ws) MMA_STEP(6, Ws) MMA_STEP(7, Ws)
        }
        __syncthreads();
    }

    const int r0 = row0 + mr;
    const int r1 = r0 + 8;
    EPI_STEP(0, g_h2h, F_OUT) EPI_STEP(1, g_h2h, F_OUT)
    EPI_STEP(2, g_h2h, F_OUT) EPI_STEP(3, g_h2h, F_OUT)
    EPI_STEP(4, g_h2h, F_OUT) EPI_STEP(5, g_h2h, F_OUT)
    EPI_STEP(6, g_h2h, F_OUT) EPI_STEP(7, g_h2h, F_OUT)
}

// ---------------------------------------------------------------------------
// scan (3 phases)
// ---------------------------------------------------------------------------
__global__ void scan_local_kernel(int N) {
    __shared__ int sh[SCAN_CHUNK];
    int tid = threadIdx.x;
    int gi = blockIdx.x * SCAN_CHUNK + tid;
    int v = (gi < N) ? g_deg[gi] : 0;
    sh[tid] = v;
    __syncthreads();
    for (int off = 1; off < SCAN_CHUNK; off <<= 1) {
        int t = 0;
        if (tid >= off) t = sh[tid - off];
        __syncthreads();
        if (tid >= off) sh[tid] += t;
        __syncthreads();
    }
    if (gi < N) g_rowptr[gi] = sh[tid] - v;
    if (tid == SCAN_CHUNK - 1) g_bsum[blockIdx.x] = sh[tid];
}

__global__ void scan_bsum_kernel(int nblk, int N) {
    __shared__ int sh[128];
    int tid = threadIdx.x;
    int v = (tid < nblk) ? g_bsum[tid] : 0;
    sh[tid] = v;
    __syncthreads();
    for (int off = 1; off < 128; off <<= 1) {
        int t = 0;
        if (tid >= off) t = sh[tid - off];
        __syncthreads();
        if (tid >= off) sh[tid] += t;
        __syncthreads();
    }
    if (tid < nblk) g_boff[tid] = sh[tid] - v;
    if (tid == 127) g_rowptr[N] = sh[127];
}

__global__ void scan_finalize_kernel(int N) {
    int gi = blockIdx.x * blockDim.x + threadIdx.x;
    if (gi < N) {
        int rp = g_rowptr[gi] + g_boff[gi / SCAN_CHUNK];
        g_rowptr[gi] = rp;
        g_cursor[gi] = rp;
        g_dinv[gi] = rsqrtf((float)(g_deg[gi] + 1));
    }
}

__global__ void csr_fill_kernel(int E) {
    int stride = gridDim.x * blockDim.x;
    for (int e = blockIdx.x * blockDim.x + threadIdx.x; e < E; e += stride) {
        int d = g_dst[e];
        int pos = atomicAdd(&g_cursor[d], 1);
        g_csrc[pos] = g_src[e];
    }
}

// ---------------------------------------------------------------------------
// agg1: warp per dst row; gathers fp16 h1, fp32 accumulate; fused bias+relu.
// ---------------------------------------------------------------------------
__global__ void agg1_kernel(const float* __restrict__ b1, int N) {
    int lane = threadIdx.x & 31;
    int warp = (blockIdx.x * blockDim.x + threadIdx.x) >> 5;
    int nwarps = (gridDim.x * blockDim.x) >> 5;
    float4 bb = *reinterpret_cast<const float4*>(&b1[lane * 4]);
    for (int r = warp; r < N; r += nwarps) {
        float dr = g_dinv[r];
        float d2 = dr * dr;
        size_t rbase = (size_t)r * F_MID + lane * 4;
        __half2 sa = *reinterpret_cast<const __half2*>(&g_h1h[rbase]);
        __half2 sb = *reinterpret_cast<const __half2*>(&g_h1h[rbase + 2]);
        float2 f0 = __half22float2(sa);
        float2 f1 = __half22float2(sb);
        float ax = f0.x * d2, ay = f0.y * d2, az = f1.x * d2, aw = f1.y * d2;

        int beg = g_rowptr[r];
        int end = g_rowptr[r + 1];
        int e = beg;
        for (; e + 1 < end; e += 2) {
            int s0 = g_csrc[e];
            int s1 = g_csrc[e + 1];
            float n0 = g_dinv[s0] * dr;
            float n1 = g_dinv[s1] * dr;
            size_t b0 = (size_t)s0 * F_MID + lane * 4;
            size_t b1o = (size_t)s1 * F_MID + lane * 4;
            __half2 p0 = *reinterpret_cast<const __half2*>(&g_h1h[b0]);
            __half2 p1 = *reinterpret_cast<const __half2*>(&g_h1h[b0 + 2]);
            __half2 q0 = *reinterpret_cast<const __half2*>(&g_h1h[b1o]);
            __half2 q1 = *reinterpret_cast<const __half2*>(&g_h1h[b1o + 2]);
            float2 pa = __half22float2(p0), pb = __half22float2(p1);
            float2 qa = __half22float2(q0), qb = __half22float2(q1);
            ax += pa.x * n0 + qa.x * n1;
            ay += pa.y * n0 + qa.y * n1;
            az += pb.x * n0 + qb.x * n1;
            aw += pb.y * n0 + qb.y * n1;
        }
        if (e < end) {
            int s0 = g_csrc[e];
            float n0 = g_dinv[s0] * dr;
            size_t b0 = (size_t)s0 * F_MID + lane * 4;
            __half2 p0 = *reinterpret_cast<const __half2*>(&g_h1h[b0]);
            __half2 p1 = *reinterpret_cast<const __half2*>(&g_h1h[b0 + 2]);
            float2 pa = __half22float2(p0), pb = __half22float2(p1);
            ax += pa.x * n0;
            ay += pa.y * n0;
            az += pb.x * n0;
            aw += pb.y * n0;
        }
        float4 outv;
        outv.x = fmaxf(ax + bb.x, 0.f);
        outv.y = fmaxf(ay + bb.y, 0.f);
        outv.z = fmaxf(az + bb.z, 0.f);
        outv.w = fmaxf(aw + bb.w, 0.f);
        *reinterpret_cast<float4*>(&g_a1[rbase]) = outv;
    }
}

// ---------------------------------------------------------------------------
// agg2: warp per dst row; gathers fp16 h2; fused bias+log_softmax -> out.
// ---------------------------------------------------------------------------
__global__ void agg2_kernel(const float* __restrict__ b2,
                            float* __restrict__ out, int N) {
    int lane = threadIdx.x & 31;
    int warp = (blockIdx.x * blockDim.x + threadIdx.x) >> 5;
    int nwarps = (gridDim.x * blockDim.x) >> 5;
    float2 bb = *reinterpret_cast<const float2*>(&b2[lane * 2]);
    for (int r = warp; r < N; r += nwarps) {
        float dr = g_dinv[r];
        float d2 = dr * dr;
        size_t rbase = (size_t)r * F_OUT + lane * 2;
        float2 f = __half22float2(*reinterpret_cast<const __half2*>(&g_h2h[rbase]));
        float ax = f.x * d2, ay = f.y * d2;

        int beg = g_rowptr[r];
        int end = g_rowptr[r + 1];
        int e = beg;
        for (; e + 1 < end; e += 2) {
            int s0 = g_csrc[e];
            int s1 = g_csrc[e + 1];
            float n0 = g_dinv[s0] * dr;
            float n1 = g_dinv[s1] * dr;
            float2 p = __half22float2(
                *reinterpret_cast<const __half2*>(&g_h2h[(size_t)s0 * F_OUT + lane * 2]));
            float2 q = __half22float2(
                *reinterpret_cast<const __half2*>(&g_h2h[(size_t)s1 * F_OUT + lane * 2]));
            ax += p.x * n0 + q.x * n1;
            ay += p.y * n0 + q.y * n1;
        }
        if (e < end) {
            int s0 = g_csrc[e];
            float n0 = g_dinv[s0] * dr;
            float2 p = __half22float2(
                *reinterpret_cast<const __half2*>(&g_h2h[(size_t)s0 * F_OUT + lane * 2]));
            ax += p.x * n0;
            ay += p.y * n0;
        }
        float vx = ax + bb.x;
        float vy = ay + bb.y;
        float m = fmaxf(vx, vy);
#pragma unroll
        for (int o = 16; o; o >>= 1) m = fmaxf(m, __shfl_xor_sync(0xffffffffu, m, o));
        float s = __expf(vx - m) + __expf(vy - m);
#pragma unroll
        for (int o = 16; o; o >>= 1) s += __shfl_xor_sync(0xffffffffu, s, o);
        float lse = m + __logf(s);
        *reinterpret_cast<float2*>(&out[rbase]) = make_float2(vx - lse, vy - lse);
    }
}

// ---------------------------------------------------------------------------
extern "C" void kernel_launch(void* const* d_in, const int* in_sizes, int n_in,
                              void* d_out, int out_size) {
    const float* x  = (const float*)d_in[0];
    const void*  ei = d_in[1];
    const float* W1 = (const float*)d_in[2];
    const float* b1 = (const float*)d_in[3];
    const float* W2 = (const float*)d_in[4];
    const float* b2 = (const float*)d_in[5];
    float* out = (float*)d_out;

    int N = in_sizes[0] / F_IN;     // 100000
    int E = in_sizes[1] / 2;        // 1600000
    if (N > NMAX) N = NMAX;
    if (E > EMAX) E = EMAX;

    int nblk_scan = (N + SCAN_CHUNK - 1) / SCAN_CHUNK;
    int grows = (N + 127) / 128;

    detect_kernel<<<1, 32>>>((const int*)ei);
    zero_deg_kernel<<<(N + 255) / 256, 256>>>(N);
    edge_prep_kernel<<<2048, 256>>>(ei, E, N);
    gemm1_kernel<<<dim3(grows, 2), 256>>>(x, W1, N);   // #4: ncu slot
    scan_local_kernel<<<nblk_scan, SCAN_CHUNK>>>(N);
    scan_bsum_kernel<<<1, 128>>>(nblk_scan, N);
    scan_finalize_kernel<<<(N + 255) / 256, 256>>>(N);
    csr_fill_kernel<<<2048, 256>>>(E);
    agg1_kernel<<<(N * 32 + 255) / 256, 256>>>(b1, N);
    gemm2_kernel<<<grows, 256>>>(W2, N);
    agg2_kernel<<<(N * 32 + 255) / 256, 256>>>(b2, out, N);
}

// round 17
// speedup vs baseline: 1.5614x; 1.0491x over previous
#include <cuda_runtime.h>
#include <cuda_fp16.h>
#include <cstdint>

// ---------------------------------------------------------------------------
// SimpleGCN R16 = R15 (236.5us, fp16 HMMA GEMMs) + traffic eliminations:
//  - g_a1 stored fp16 (rounding point moves from gemm2's fill to agg1's store
//    = bit-identical result, saves 50MB round trip)
//  - g_src/g_dst eliminated (csr_fill re-decodes edge_index; net -25MB)
//  - zero_deg merged into detect kernel
// ---------------------------------------------------------------------------

#define NMAX 100000
#define EMAX 1600000
#define F_IN 128
#define F_MID 128
#define F_OUT 64

#define SCAN_CHUNK 1024
#define NBLK_SCAN ((NMAX + SCAN_CHUNK - 1) / SCAN_CHUNK)

#define APH 72   // A smem pitch in halves (144 B)
#define WPH 72   // W smem pitch in halves

__device__ __align__(16) int    g_csrc[EMAX];
__device__ __align__(16) int    g_deg[NMAX];
__device__ __align__(16) int    g_rowptr[NMAX + 1];
__device__ __align__(16) int    g_cursor[NMAX];
__device__ __align__(16) int    g_bsum[NBLK_SCAN];
__device__ __align__(16) int    g_boff[NBLK_SCAN];
__device__ __align__(16) float  g_dinv[NMAX];
__device__ __align__(16) __half g_h1h[(size_t)NMAX * F_MID];  // fp16(x@W1)
__device__ __align__(16) __half g_a1h[(size_t)NMAX * F_MID];  // fp16(relu(agg+b1))
__device__ __align__(16) __half g_h2h[(size_t)NMAX * F_OUT];  // fp16(a1@W2)
__device__ int g_is64;

// ---------------------------------------------------------------------------
// 0+1. detect dtype (1 thread) + zero deg (whole grid)
// ---------------------------------------------------------------------------
__global__ void detect_zero_kernel(const int* __restrict__ ei32, int N) {
    int i = blockIdx.x * blockDim.x + threadIdx.x;
    if (i < N) g_deg[i] = 0;
    if (i == 0) {
        int allzero = 1;
        for (int k = 0; k < 64; k++)
            if (ei32[2 * k + 1] != 0) { allzero = 0; break; }
        g_is64 = allzero;
    }
}

// ---------------------------------------------------------------------------
// 2. histogram only (no src/dst store)
// ---------------------------------------------------------------------------
__global__ void edge_prep_kernel(const void* __restrict__ ei_raw, int E, int N) {
    const int is64 = g_is64;
    const int stride = gridDim.x * blockDim.x;
    const int* __restrict__ p32 = (const int*)ei_raw;
    const long long* __restrict__ p64 = (const long long*)ei_raw;
    for (int e = blockIdx.x * blockDim.x + threadIdx.x; e < E; e += stride) {
        int d = is64 ? (int)p64[(size_t)E + e] : p32[(size_t)E + e];
        d = min(max(d, 0), N - 1);
        atomicAdd(&g_deg[d], 1);
    }
}

// ---------------------------------------------------------------------------
// HMMA helpers
// ---------------------------------------------------------------------------
#define HMMA(c0, c1, c2, c3, a0, a1, a2, a3, b0, b1)                          \
    asm volatile(                                                             \
        "mma.sync.aligned.m16n8k16.row.col.f32.f16.f16.f32 "                  \
        "{%0,%1,%2,%3}, {%4,%5,%6,%7}, {%8,%9}, {%0,%1,%2,%3};"               \
        : "+f"(c0), "+f"(c1), "+f"(c2), "+f"(c3)                              \
        : "r"(a0), "r"(a1), "r"(a2), "r"(a3), "r"(b0), "r"(b1));

#define DECLC(i) float c##i##0 = 0.f, c##i##1 = 0.f, c##i##2 = 0.f, c##i##3 = 0.f;

#define MMA_STEP(i, Ws)                                                       \
    {                                                                         \
        uint32_t b0 = *reinterpret_cast<const uint32_t*>(                     \
            &Ws[((i) * 8 + g) * WPH + kb + 2 * t]);                           \
        uint32_t b1 = *reinterpret_cast<const uint32_t*>(                     \
            &Ws[((i) * 8 + g) * WPH + kb + 2 * t + 8]);                       \
        HMMA(c##i##0, c##i##1, c##i##2, c##i##3, a0, a1, a2, a3, b0, b1);     \
    }

#define EPI_STEP(i, OUT, OSTR)                                                \
    {                                                                         \
        int col = col0 + (i) * 8 + 2 * t;                                     \
        if (r0 < N)                                                           \
            *reinterpret_cast<__half2*>(&OUT[(size_t)r0 * (OSTR) + col]) =    \
                __floats2half2_rn(c##i##0, c##i##1);                          \
        if (r1 < N)                                                           \
            *reinterpret_cast<__half2*>(&OUT[(size_t)r1 * (OSTR) + col]) =    \
                __floats2half2_rn(c##i##2, c##i##3);                          \
    }

// ---------------------------------------------------------------------------
// GEMM1: g_h1h = fp16(x @ W1). Block 128x64 (grid.y = 2 col slabs),
// 8 warps, warp = 16 rows x 64 cols; fp16 smem operands, fp32 accum.
// ---------------------------------------------------------------------------
__global__ __launch_bounds__(256)
void gemm1_kernel(const float* __restrict__ X,
                  const float* __restrict__ W, int N) {
    __shared__ __align__(16) __half As[128 * APH];
    __shared__ __align__(16) __half Ws[64 * WPH];

    const int tid = threadIdx.x;
    const int lane = tid & 31;
    const int w = tid >> 5;
    const int g = lane >> 2;
    const int t = lane & 3;
    const int row0 = blockIdx.x * 128;
    const int col0 = blockIdx.y * 64;
    const int mr = w * 16 + g;

    DECLC(0) DECLC(1) DECLC(2) DECLC(3) DECLC(4) DECLC(5) DECLC(6) DECLC(7)

    for (int kc = 0; kc < F_IN; kc += 64) {
#pragma unroll
        for (int it = 0; it < 8; it++) {
            int idx = tid + it * 256;
            int r = idx >> 4;
            int c4 = idx & 15;
            int gr = row0 + r;
            float4 v = make_float4(0.f, 0.f, 0.f, 0.f);
            if (gr < N)
                v = *reinterpret_cast<const float4*>(&X[(size_t)gr * F_IN + kc + c4 * 4]);
            *reinterpret_cast<__half2*>(&As[r * APH + c4 * 4]) = __floats2half2_rn(v.x, v.y);
            *reinterpret_cast<__half2*>(&As[r * APH + c4 * 4 + 2]) = __floats2half2_rn(v.z, v.w);
        }
#pragma unroll
        for (int it = 0; it < 8; it++) {
            int idx = tid + it * 256;
            int k2 = idx >> 6;
            int n = idx & 63;
            float w0 = W[(size_t)(kc + 2 * k2) * F_MID + col0 + n];
            float w1 = W[(size_t)(kc + 2 * k2 + 1) * F_MID + col0 + n];
            *reinterpret_cast<__half2*>(&Ws[n * WPH + 2 * k2]) = __floats2half2_rn(w0, w1);
        }
        __syncthreads();

#pragma unroll
        for (int ks = 0; ks < 4; ks++) {
            const int kb = ks * 16;
            uint32_t a0 = *reinterpret_cast<const uint32_t*>(&As[mr * APH + kb + 2 * t]);
            uint32_t a1 = *reinterpret_cast<const uint32_t*>(&As[(mr + 8) * APH + kb + 2 * t]);
            uint32_t a2 = *reinterpret_cast<const uint32_t*>(&As[mr * APH + kb + 2 * t + 8]);
            uint32_t a3 = *reinterpret_cast<const uint32_t*>(&As[(mr + 8) * APH + kb + 2 * t + 8]);
            MMA_STEP(0, Ws) MMA_STEP(1, Ws) MMA_STEP(2, Ws) MMA_STEP(3, Ws)
            MMA_STEP(4, Ws) MMA_STEP(5, Ws) MMA_STEP(6, Ws) MMA_STEP(7, Ws)
        }
        __syncthreads();
    }

    const int r0 = row0 + mr;
    const int r1 = r0 + 8;
    EPI_STEP(0, g_h1h, F_MID) EPI_STEP(1, g_h1h, F_MID)
    EPI_STEP(2, g_h1h, F_MID) EPI_STEP(3, g_h1h, F_MID)
    EPI_STEP(4, g_h1h, F_MID) EPI_STEP(5, g_h1h, F_MID)
    EPI_STEP(6, g_h1h, F_MID) EPI_STEP(7, g_h1h, F_MID)
}

// ---------------------------------------------------------------------------
// GEMM2: g_h2h = fp16(g_a1h @ W2). A already fp16 -> direct uint4 loads.
// ---------------------------------------------------------------------------
__global__ __launch_bounds__(256)
void gemm2_kernel(const float* __restrict__ W, int N) {
    __shared__ __align__(16) __half As[128 * APH];
    __shared__ __align__(16) __half Ws[64 * WPH];

    const int tid = threadIdx.x;
    const int lane = tid & 31;
    const int w = tid >> 5;
    const int g = lane >> 2;
    const int t = lane & 3;
    const int row0 = blockIdx.x * 128;
    const int col0 = 0;
    const int mr = w * 16 + g;

    DECLC(0) DECLC(1) DECLC(2) DECLC(3) DECLC(4) DECLC(5) DECLC(6) DECLC(7)

    for (int kc = 0; kc < F_MID; kc += 64) {
        // A fill: 128 rows x 64 halves = 128 B/row = 8 uint4/row; 4/thread.
#pragma unroll
        for (int it = 0; it < 4; it++) {
            int idx = tid + it * 256;
            int r = idx >> 3;
            int c8 = idx & 7;
            int gr = row0 + r;
            uint4 v = make_uint4(0u, 0u, 0u, 0u);
            if (gr < N)
                v = *reinterpret_cast<const uint4*>(&g_a1h[(size_t)gr * F_MID + kc + c8 * 8]);
            *reinterpret_cast<uint4*>(&As[r * APH + c8 * 8]) = v;
        }
#pragma unroll
        for (int it = 0; it < 8; it++) {
            int idx = tid + it * 256;
            int k2 = idx >> 6;
            int n = idx & 63;
            float w0 = W[(size_t)(kc + 2 * k2) * F_OUT + n];
            float w1 = W[(size_t)(kc + 2 * k2 + 1) * F_OUT + n];
            *reinterpret_cast<__half2*>(&Ws[n * WPH + 2 * k2]) = __floats2half2_rn(w0, w1);
        }
        __syncthreads();

#pragma unroll
        for (int ks = 0; ks < 4; ks++) {
            const int kb = ks * 16;
            uint32_t a0 = *reinterpret_cast<const uint32_t*>(&As[mr * APH + kb + 2 * t]);
            uint32_t a1 = *reinterpret_cast<const uint32_t*>(&As[(mr + 8) * APH + kb + 2 * t]);
            uint32_t a2 = *reinterpret_cast<const uint32_t*>(&As[mr * APH + kb + 2 * t + 8]);
            uint32_t a3 = *reinterpret_cast<const uint32_t*>(&As[(mr + 8) * APH + kb + 2 * t + 8]);
            MMA_STEP(0, Ws) MMA_STEP(1, Ws) MMA_STEP(2, Ws) MMA_STEP(3, Ws)
            MMA_STEP(4, Ws) MMA_STEP(5, Ws) MMA_STEP(6, Ws) MMA_STEP(7, Ws)
        }
        __syncthreads();
    }

    const int r0 = row0 + mr;
    const int r1 = r0 + 8;
    EPI_STEP(0, g_h2h, F_OUT) EPI_STEP(1, g_h2h, F_OUT)
    EPI_STEP(2, g_h2h, F_OUT) EPI_STEP(3, g_h2h, F_OUT)
    EPI_STEP(4, g_h2h, F_OUT) EPI_STEP(5, g_h2h, F_OUT)
    EPI_STEP(6, g_h2h, F_OUT) EPI_STEP(7, g_h2h, F_OUT)
}

// ---------------------------------------------------------------------------
// scan (3 phases)
// ---------------------------------------------------------------------------
__global__ void scan_local_kernel(int N) {
    __shared__ int sh[SCAN_CHUNK];
    int tid = threadIdx.x;
    int gi = blockIdx.x * SCAN_CHUNK + tid;
    int v = (gi < N) ? g_deg[gi] : 0;
    sh[tid] = v;
    __syncthreads();
    for (int off = 1; off < SCAN_CHUNK; off <<= 1) {
        int t = 0;
        if (tid >= off) t = sh[tid - off];
        __syncthreads();
        if (tid >= off) sh[tid] += t;
        __syncthreads();
    }
    if (gi < N) g_rowptr[gi] = sh[tid] - v;
    if (tid == SCAN_CHUNK - 1) g_bsum[blockIdx.x] = sh[tid];
}

__global__ void scan_bsum_kernel(int nblk, int N) {
    __shared__ int sh[128];
    int tid = threadIdx.x;
    int v = (tid < nblk) ? g_bsum[tid] : 0;
    sh[tid] = v;
    __syncthreads();
    for (int off = 1; off < 128; off <<= 1) {
        int t = 0;
        if (tid >= off) t = sh[tid - off];
        __syncthreads();
        if (tid >= off) sh[tid] += t;
        __syncthreads();
    }
    if (tid < nblk) g_boff[tid] = sh[tid] - v;
    if (tid == 127) g_rowptr[N] = sh[127];
}

__global__ void scan_finalize_kernel(int N) {
    int gi = blockIdx.x * blockDim.x + threadIdx.x;
    if (gi < N) {
        int rp = g_rowptr[gi] + g_boff[gi / SCAN_CHUNK];
        g_rowptr[gi] = rp;
        g_cursor[gi] = rp;
        g_dinv[gi] = rsqrtf((float)(g_deg[gi] + 1));
    }
}

// ---------------------------------------------------------------------------
// csr_fill: decode edges directly (no src/dst arrays)
// ---------------------------------------------------------------------------
__global__ void csr_fill_kernel(const void* __restrict__ ei_raw, int E, int N) {
    const int is64 = g_is64;
    const int stride = gridDim.x * blockDim.x;
    const int* __restrict__ p32 = (const int*)ei_raw;
    const long long* __restrict__ p64 = (const long long*)ei_raw;
    for (int e = blockIdx.x * blockDim.x + threadIdx.x; e < E; e += stride) {
        int s, d;
        if (is64) {
            s = (int)p64[e];
            d = (int)p64[(size_t)E + e];
        } else {
            s = p32[e];
            d = p32[(size_t)E + e];
        }
        s = min(max(s, 0), N - 1);
        d = min(max(d, 0), N - 1);
        int pos = atomicAdd(&g_cursor[d], 1);
        g_csrc[pos] = s;
    }
}

// ---------------------------------------------------------------------------
// agg1: warp per dst row; gathers fp16 h1, fp32 accumulate; fused bias+relu;
// writes fp16 a1 (same rounding point gemm2 would apply anyway).
// ---------------------------------------------------------------------------
__global__ void agg1_kernel(const float* __restrict__ b1, int N) {
    int lane = threadIdx.x & 31;
    int warp = (blockIdx.x * blockDim.x + threadIdx.x) >> 5;
    int nwarps = (gridDim.x * blockDim.x) >> 5;
    float4 bb = *reinterpret_cast<const float4*>(&b1[lane * 4]);
    for (int r = warp; r < N; r += nwarps) {
        float dr = g_dinv[r];
        float d2 = dr * dr;
        size_t rbase = (size_t)r * F_MID + lane * 4;
        __half2 sa = *reinterpret_cast<const __half2*>(&g_h1h[rbase]);
        __half2 sb = *reinterpret_cast<const __half2*>(&g_h1h[rbase + 2]);
        float2 f0 = __half22float2(sa);
        float2 f1 = __half22float2(sb);
        float ax = f0.x * d2, ay = f0.y * d2, az = f1.x * d2, aw = f1.y * d2;

        int beg = g_rowptr[r];
        int end = g_rowptr[r + 1];
        int e = beg;
        for (; e + 1 < end; e += 2) {
            int s0 = g_csrc[e];
            int s1 = g_csrc[e + 1];
            float n0 = g_dinv[s0] * dr;
            float n1 = g_dinv[s1] * dr;
            size_t b0 = (size_t)s0 * F_MID + lane * 4;
            size_t b1o = (size_t)s1 * F_MID + lane * 4;
            __half2 p0 = *reinterpret_cast<const __half2*>(&g_h1h[b0]);
            __half2 p1 = *reinterpret_cast<const __half2*>(&g_h1h[b0 + 2]);
            __half2 q0 = *reinterpret_cast<const __half2*>(&g_h1h[b1o]);
            __half2 q1 = *reinterpret_cast<const __half2*>(&g_h1h[b1o + 2]);
            float2 pa = __half22float2(p0), pb = __half22float2(p1);
            float2 qa = __half22float2(q0), qb = __half22float2(q1);
            ax += pa.x * n0 + qa.x * n1;
            ay += pa.y * n0 + qa.y * n1;
            az += pb.x * n0 + qb.x * n1;
            aw += pb.y * n0 + qb.y * n1;
        }
        if (e < end) {
            int s0 = g_csrc[e];
            float n0 = g_dinv[s0] * dr;
            size_t b0 = (size_t)s0 * F_MID + lane * 4;
            __half2 p0 = *reinterpret_cast<const __half2*>(&g_h1h[b0]);
            __half2 p1 = *reinterpret_cast<const __half2*>(&g_h1h[b0 + 2]);
            float2 pa = __half22float2(p0), pb = __half22float2(p1);
            ax += pa.x * n0;
            ay += pa.y * n0;
            az += pb.x * n0;
            aw += pb.y * n0;
        }
        float vx = fmaxf(ax + bb.x, 0.f);
        float vy = fmaxf(ay + bb.y, 0.f);
        float vz = fmaxf(az + bb.z, 0.f);
        float vw = fmaxf(aw + bb.w, 0.f);
        *reinterpret_cast<__half2*>(&g_a1h[rbase]) = __floats2half2_rn(vx, vy);
        *reinterpret_cast<__half2*>(&g_a1h[rbase + 2]) = __floats2half2_rn(vz, vw);
    }
}

// ---------------------------------------------------------------------------
// agg2: warp per dst row; gathers fp16 h2; fused bias+log_softmax -> out.
// ---------------------------------------------------------------------------
__global__ void agg2_kernel(const float* __restrict__ b2,
                            float* __restrict__ out, int N) {
    int lane = threadIdx.x & 31;
    int warp = (blockIdx.x * blockDim.x + threadIdx.x) >> 5;
    int nwarps = (gridDim.x * blockDim.x) >> 5;
    float2 bb = *reinterpret_cast<const float2*>(&b2[lane * 2]);
    for (int r = warp; r < N; r += nwarps) {
        float dr = g_dinv[r];
        float d2 = dr * dr;
        size_t rbase = (size_t)r * F_OUT + lane * 2;
        float2 f = __half22float2(*reinterpret_cast<const __half2*>(&g_h2h[rbase]));
        float ax = f.x * d2, ay = f.y * d2;

        int beg = g_rowptr[r];
        int end = g_rowptr[r + 1];
        int e = beg;
        for (; e + 1 < end; e += 2) {
            int s0 = g_csrc[e];
            int s1 = g_csrc[e + 1];
            float n0 = g_dinv[s0] * dr;
            float n1 = g_dinv[s1] * dr;
            float2 p = __half22float2(
                *reinterpret_cast<const __half2*>(&g_h2h[(size_t)s0 * F_OUT + lane * 2]));
            float2 q = __half22float2(
                *reinterpret_cast<const __half2*>(&g_h2h[(size_t)s1 * F_OUT + lane * 2]));
            ax += p.x * n0 + q.x * n1;
            ay += p.y * n0 + q.y * n1;
        }
        if (e < end) {
            int s0 = g_csrc[e];
            float n0 = g_dinv[s0] * dr;
            float2 p = __half22float2(
                *reinterpret_cast<const __half2*>(&g_h2h[(size_t)s0 * F_OUT + lane * 2]));
            ax += p.x * n0;
            ay += p.y * n0;
        }
        float vx = ax + bb.x;
        float vy = ay + bb.y;
        float m = fmaxf(vx, vy);
#pragma unroll
        for (int o = 16; o; o >>= 1) m = fmaxf(m, __shfl_xor_sync(0xffffffffu, m, o));
        float s = __expf(vx - m) + __expf(vy - m);
#pragma unroll
        for (int o = 16; o; o >>= 1) s += __shfl_xor_sync(0xffffffffu, s, o);
        float lse = m + __logf(s);
        *reinterpret_cast<float2*>(&out[rbase]) = make_float2(vx - lse, vy - lse);
    }
}

// ---------------------------------------------------------------------------
extern "C" void kernel_launch(void* const* d_in, const int* in_sizes, int n_in,
                              void* d_out, int out_size) {
    const float* x  = (const float*)d_in[0];
    const void*  ei = d_in[1];
    const float* W1 = (const float*)d_in[2];
    const float* b1 = (const float*)d_in[3];
    const float* W2 = (const float*)d_in[4];
    const float* b2 = (const float*)d_in[5];
    float* out = (float*)d_out;

    int N = in_sizes[0] / F_IN;     // 100000
    int E = in_sizes[1] / 2;        // 1600000
    if (N > NMAX) N = NMAX;
    if (E > EMAX) E = EMAX;

    int nblk_scan = (N + SCAN_CHUNK - 1) / SCAN_CHUNK;
    int grows = (N + 127) / 128;

    detect_zero_kernel<<<(N + 255) / 256, 256>>>((const int*)ei, N);
    edge_prep_kernel<<<2048, 256>>>(ei, E, N);
    gemm1_kernel<<<dim3(grows, 2), 256>>>(x, W1, N);   // #3
    scan_local_kernel<<<nblk_scan, SCAN_CHUNK>>>(N);   // #4: ncu slot
    scan_bsum_kernel<<<1, 128>>>(nblk_scan, N);
    scan_finalize_kernel<<<(N + 255) / 256, 256>>>(N);
    csr_fill_kernel<<<2048, 256>>>(ei, E, N);
    agg1_kernel<<<(N * 32 + 255) / 256, 256>>>(b1, N);
    gemm2_kernel<<<grows, 256>>>(W2, N);
    agg2_kernel<<<(N * 32 + 255) / 256, 256>>>(b2, out, N);
}